// round 6
// baseline (speedup 1.0000x reference)
#include <cuda_runtime.h>

#define NB 2
#define CIN 1024
#define CMID 1024
#define HH 50
#define WW 50
#define SPAT 2500
#define RR 300
#define PQN 49
#define NCLS 21
#define COMB 25

// ---------------- scratch (static device memory; no allocations) ----------------
__device__ float4 g_h1t4[(size_t)NB * SPAT * (CMID / 4)];  // h1 (tf32-rounded), [n*2500+s][o]
__device__ float  g_scr[(size_t)RR * COMB * PQN];          // per-(roi,c,pq) pooled values

// round fp32 -> tf32 value (kept in fp32 storage)
__device__ __forceinline__ float tf32r(float x) {
  unsigned u;
  asm("cvt.rna.tf32.f32 %0, %1;" : "=r"(u) : "f"(x));
  return __uint_as_float(u);
}
__device__ __forceinline__ float4 tf32r4(float4 v) {
  return make_float4(tf32r(v.x), tf32r(v.y), tf32r(v.z), tf32r(v.w));
}

// ---------------- 1. GEMM1: h1t[n*2500+s][o] = tf32(sum_c tf32(h[n,c,s])*tf32(w1[o,c]) + b1[o])
__global__ __launch_bounds__(256) void k_gemm1(const float* __restrict__ h,
                                               const float* __restrict__ w1,
                                               const float* __restrict__ b1) {
  __shared__ float As[16][128];   // [k][m]  (m = spatial s)
  __shared__ float Bs[16][128];   // [k][n]  (n = output channel o)
  int t = threadIdx.x;
  int n0 = blockIdx.x * 128;      // o tile
  int s0 = blockIdx.y * 128;      // s tile
  int nb = blockIdx.z;            // batch
  int tx = t & 15, ty = t >> 4;

  float acc[8][8];
#pragma unroll
  for (int i = 0; i < 8; i++)
#pragma unroll
    for (int j = 0; j < 8; j++) acc[i][j] = 0.f;

  const float* hbase = h + (size_t)nb * CIN * SPAT;

  for (int k0 = 0; k0 < CIN; k0 += 16) {
#pragma unroll
    for (int i = 0; i < 2; i++) {
      int idx = i * 256 + t;
      int kk = idx >> 5;             // 0..15
      int mf = (idx & 31) << 2;      // 0..124
      float4 v = make_float4(0.f, 0.f, 0.f, 0.f);
      if (s0 + mf < SPAT)            // SPAT%4==0 so full float4 in-bounds
        v = *(const float4*)(hbase + (size_t)(k0 + kk) * SPAT + s0 + mf);
      v = tf32r4(v);
      As[kk][mf + 0] = v.x; As[kk][mf + 1] = v.y;
      As[kk][mf + 2] = v.z; As[kk][mf + 3] = v.w;
    }
#pragma unroll
    for (int i = 0; i < 2; i++) {
      int idx = i * 256 + t;
      int ol = idx >> 2;             // 0..127
      int cq = (idx & 3) << 2;       // 0,4,8,12
      float4 v = *(const float4*)(w1 + (size_t)(n0 + ol) * CIN + k0 + cq);
      v = tf32r4(v);
      Bs[cq + 0][ol] = v.x; Bs[cq + 1][ol] = v.y;
      Bs[cq + 2][ol] = v.z; Bs[cq + 3][ol] = v.w;
    }
    __syncthreads();
#pragma unroll
    for (int kk = 0; kk < 16; kk++) {
      float4 aA = *(float4*)&As[kk][tx << 2];
      float4 aB = *(float4*)&As[kk][64 + (tx << 2)];
      float4 bA = *(float4*)&Bs[kk][ty << 2];
      float4 bB = *(float4*)&Bs[kk][64 + (ty << 2)];
      float a[8] = {aA.x, aA.y, aA.z, aA.w, aB.x, aB.y, aB.z, aB.w};
      float b[8] = {bA.x, bA.y, bA.z, bA.w, bB.x, bB.y, bB.z, bB.w};
#pragma unroll
      for (int i = 0; i < 8; i++)
#pragma unroll
        for (int j = 0; j < 8; j++) acc[i][j] += a[i] * b[j];
    }
    __syncthreads();
  }

  float4 g0 = *(const float4*)(b1 + n0 + (ty << 2));
  float4 g1 = *(const float4*)(b1 + n0 + 64 + (ty << 2));
  float bb[8] = {g0.x, g0.y, g0.z, g0.w, g1.x, g1.y, g1.z, g1.w};
  float* h1t = (float*)g_h1t4;
#pragma unroll
  for (int i = 0; i < 8; i++) {
    int ml = (i < 4) ? ((tx << 2) + i) : (64 + (tx << 2) + i - 4);
    int s = s0 + ml;
    if (s >= SPAT) continue;
    float* rowp = h1t + ((size_t)(nb * SPAT + s) << 10) + n0;
    float o0[4], o1[4];
#pragma unroll
    for (int j = 0; j < 4; j++) o0[j] = tf32r(acc[i][j] + bb[j]);
#pragma unroll
    for (int j = 0; j < 4; j++) o1[j] = tf32r(acc[i][j + 4] + bb[j + 4]);
    *(float4*)(rowp + (ty << 2)) = make_float4(o0[0], o0[1], o0[2], o0[3]);
    *(float4*)(rowp + 64 + (ty << 2)) = make_float4(o1[0], o1[1], o1[2], o1[3]);
  }
}

// ---------------- roi geometry: XLA semantics (div-by-const -> reciprocal mul) ------
__device__ __forceinline__ void roi_geom(const float* __restrict__ rois, int r, int p, int q,
                                         int& hs, int& he, int& ws, int& we) {
  float x1 = rois[4 * r + 0], y1 = rois[4 * r + 1];
  float x2 = rois[4 * r + 2], y2 = rois[4 * r + 3];
  float sw = __fmul_rn(rintf(x1), 0.0625f);
  float sh = __fmul_rn(rintf(y1), 0.0625f);
  float ew = __fmul_rn(rintf(__fadd_rn(x2, 1.0f)), 0.0625f);
  float eh = __fmul_rn(rintf(__fadd_rn(y2, 1.0f)), 0.0625f);
  float rw = fmaxf(__fadd_rn(ew, -sw), 0.1f);
  float rh = fmaxf(__fadd_rn(eh, -sh), 0.1f);
  // XLA: roi / 7  ->  roi * fl(1/7)
  const float RSEV = 1.0f / 7.0f;   // 0x3E124925, compile-time RN(1/7)
  float bh = __fmul_rn(rh, RSEV);
  float bw = __fmul_rn(rw, RSEV);
  float fp = (float)p, fq = (float)q;
  hs = (int)fminf(fmaxf(floorf(__fadd_rn(__fmul_rn(fp, bh), sh)), 0.f), 50.f);
  he = (int)fminf(fmaxf(ceilf(__fadd_rn(__fmul_rn(__fadd_rn(fp, 1.f), bh), sh)), 0.f), 50.f);
  ws = (int)fminf(fmaxf(floorf(__fadd_rn(__fmul_rn(fq, bw), sw)), 0.f), 50.f);
  we = (int)fminf(fmaxf(ceilf(__fadd_rn(__fmul_rn(__fadd_rn(fq, 1.f), bw), sw)), 0.f), 50.f);
}

// ---------------- 2. fused pool + 25-row projection ----------------
__global__ __launch_bounds__(256) void k_pool(const float* __restrict__ rois,
                                              const int* __restrict__ ridx,
                                              const float* __restrict__ wc,
                                              const float* __restrict__ wl,
                                              const float* __restrict__ bc,
                                              const float* __restrict__ bl) {
  int pq = blockIdx.x;
  int g = blockIdx.y;
  int p = pq / 7, q = pq - p * 7;
  int tid = threadIdx.x;
  int lane = tid & 31, warp = tid >> 5;

  float4 wreg[COMB];
#pragma unroll
  for (int c = 0; c < COMB; c++) {
    const float* wrow = (c < NCLS) ? (wc + ((size_t)(c * PQN + pq) << 10))
                                   : (wl + ((size_t)((c - NCLS) * PQN + pq) << 10));
    wreg[c] = tf32r4(*(const float4*)(wrow + (tid << 2)));
  }

  __shared__ float red[COMB][8];

  for (int rr = 0; rr < 30; rr++) {
    int r = g * 30 + rr;
    int hs, he, ws, we;
    roi_geom(rois, r, p, q, hs, he, ws, we);
    int n = ridx[r];

    float4 acc = make_float4(0.f, 0.f, 0.f, 0.f);
    const float4* base = g_h1t4 + ((size_t)n * SPAT) * 256 + tid;
    for (int y = hs; y < he; y++) {
      const float4* rowp = base + (size_t)(y * WW) * 256;
      for (int x = ws; x < we; x++) {
        float4 v = __ldg(rowp + (size_t)x * 256);
        acc.x += v.x; acc.y += v.y; acc.z += v.z; acc.w += v.w;
      }
    }

#pragma unroll
    for (int c = 0; c < COMB; c++) {
      float s = acc.x * wreg[c].x + acc.y * wreg[c].y + acc.z * wreg[c].z + acc.w * wreg[c].w;
#pragma unroll
      for (int off = 16; off; off >>= 1) s += __shfl_xor_sync(0xffffffffu, s, off);
      if (lane == 0) red[c][warp] = s;
    }
    __syncthreads();

    if (tid < COMB) {
      int c = tid;
      float s = 0.f;
#pragma unroll
      for (int w = 0; w < 8; w++) s += red[c][w];
      int cnt = (he - hs) * (we - ws);
      float val = 0.f;
      if (cnt > 0) {
        float bias = (c < NCLS) ? bc[c * PQN + pq] : bl[(c - NCLS) * PQN + pq];
        val = __fadd_rn(__fdiv_rn(s, (float)cnt), bias);   // pooled bin value (bias inside feat)
      }
      g_scr[((size_t)r * COMB + c) * PQN + pq] = val;
    }
    __syncthreads();
  }
}

// ---------------- 3. reduce: mean over 49 bins = sum * fl(1/49)  ----------------
__global__ void k_reduce(float* __restrict__ out) {
  int idx = blockIdx.x * blockDim.x + threadIdx.x;
  if (idx >= RR * COMB) return;
  int r = idx / COMB, c = idx - r * COMB;
  const float* src = g_scr + (size_t)idx * PQN;
  float s = 0.f;
#pragma unroll
  for (int pq = 0; pq < PQN; pq++) s += src[pq];
  float mean = __fmul_rn(s, 1.0f / 49.0f);                // XLA: mean -> sum * recip
  if (c < NCLS) out[r * NCLS + c] = mean;                  // roi_score [300,21]
  else out[RR * NCLS + r * 4 + (c - NCLS)] = mean;         // roi_locs  [300,4]
}

// ---------------- launch ----------------
extern "C" void kernel_launch(void* const* d_in, const int* in_sizes, int n_in,
                              void* d_out, int out_size) {
  const float* h    = (const float*)d_in[0];
  const float* rois = (const float*)d_in[1];
  const int*   ridx = (const int*)d_in[2];
  const float* w1   = (const float*)d_in[3];
  const float* b1   = (const float*)d_in[4];
  const float* wc   = (const float*)d_in[5];
  const float* bc   = (const float*)d_in[6];
  const float* wl   = (const float*)d_in[7];
  const float* bl   = (const float*)d_in[8];
  float* out = (float*)d_out;

  k_gemm1<<<dim3(CMID / 128, (SPAT + 127) / 128, NB), 256>>>(h, w1, b1);
  k_pool<<<dim3(PQN, 10), 256>>>(rois, ridx, wc, wl, bc, bl);
  k_reduce<<<(RR * COMB + 255) / 256, 256>>>(out);
}

// round 7
// speedup vs baseline: 1.5038x; 1.5038x over previous
#include <cuda_runtime.h>

#define NB 2
#define CIN 1024
#define HH 50
#define WW 50
#define SPAT 2500
#define SATN 51
#define SATSP (SATN * SATN)
#define RR 300
#define PQN 49
#define NCLS 21
#define ROWS_CLS 1029
#define ROWS_TOT 1225
#define COMB 25

// ---------------- scratch (static device memory; no allocations) ----------------
__device__ float4 g_ht4[(size_t)NB * SPAT * (CIN / 4)];   // tf32(h) channel-last [n][s][c4]
__device__ float4 g_sat4[(size_t)NB * SATSP * (CIN / 4)]; // SAT [n][y*51+x][c4]
__device__ float4 g_W4[(size_t)ROWS_TOT * (CIN / 4)];     // folded weights, natural row j
__device__ float  g_bias[ROWS_TOT];                       // folded bias
__device__ float  g_scr[(size_t)RR * COMB * PQN];         // per-(roi,c,pq) pooled values

// fp32 -> tf32-rounded fp32
__device__ __forceinline__ float tf32r(float x) {
  unsigned u;
  asm("cvt.rna.tf32.f32 %0, %1;" : "=r"(u) : "f"(x));
  return __uint_as_float(u);
}
__device__ __forceinline__ float4 tf32r4(float4 v) {
  return make_float4(tf32r(v.x), tf32r(v.y), tf32r(v.z), tf32r(v.w));
}

// ---------------- 1. transpose h [n,c,s] -> ht [n,s,c], tf32-rounded ----------------
__global__ void k_transpose(const float* __restrict__ h) {
  __shared__ float tile[32][33];
  int n = blockIdx.z;
  int s0 = blockIdx.x * 32, c0 = blockIdx.y * 32;
  int tx = threadIdx.x, ty = threadIdx.y;
  float* ht = (float*)g_ht4;
#pragma unroll
  for (int i = 0; i < 32; i += 8) {
    int c = c0 + ty + i, s = s0 + tx;
    if (c < CIN && s < SPAT) tile[ty + i][tx] = h[((size_t)n * CIN + c) * SPAT + s];
  }
  __syncthreads();
#pragma unroll
  for (int i = 0; i < 32; i += 8) {
    int s = s0 + ty + i, c = c0 + tx;
    if (s < SPAT && c < CIN) ht[((size_t)n * SPAT + s) * CIN + c] = tf32r(tile[tx][ty + i]);
  }
}

// ---------------- 2a. SAT pass 1: prefix along x ----------------
// grid (51, NB); block 256 = one c4 per thread. by==0 writes zero row.
__global__ __launch_bounds__(256) void k_sat1() {
  int by = blockIdx.x;
  int n = blockIdx.y;
  int tid = threadIdx.x;
  float4* satb = g_sat4 + (size_t)n * SATSP * 256;
  if (by == 0) {
    float4 z = make_float4(0.f, 0.f, 0.f, 0.f);
    for (int x = 0; x < SATN; x++) satb[(size_t)x * 256 + tid] = z;
    return;
  }
  int y = by - 1;
  const float4* src = g_ht4 + ((size_t)n * SPAT + y * WW) * 256 + tid;
  float4* dst = satb + (size_t)(by * SATN) * 256 + tid;
  float4 acc = make_float4(0.f, 0.f, 0.f, 0.f);
  dst[0] = acc;
#pragma unroll 5
  for (int x = 0; x < WW; x++) {
    float4 v = src[(size_t)x * 256];
    acc.x += v.x; acc.y += v.y; acc.z += v.z; acc.w += v.w;
    dst[(size_t)(x + 1) * 256] = acc;
  }
}

// ---------------- 2b. SAT pass 2: prefix along y (in place) ----------------
// grid (51, NB); block 256.
__global__ __launch_bounds__(256) void k_sat2() {
  int x = blockIdx.x;
  int n = blockIdx.y;
  int tid = threadIdx.x;
  float4* p = g_sat4 + ((size_t)n * SATSP + x) * 256 + tid;
  float4 acc = make_float4(0.f, 0.f, 0.f, 0.f);
#pragma unroll 5
  for (int y = 1; y < SATN; y++) {
    float4 v = p[(size_t)(y * SATN) * 256];
    acc.x += v.x; acc.y += v.y; acc.z += v.z; acc.w += v.w;
    p[(size_t)(y * SATN) * 256] = acc;
  }
}

// ---------------- 3. fold GEMM: W_comb[j,c] = sum_o A[j,o] * w1[o,c] ----------------
// 128x128x16 tiles, 256 thr, 8x8 micro, tf32-rounded inputs, fp32 accumulate.
__global__ __launch_bounds__(256) void k_fold(const float* __restrict__ A,
                                              const float* __restrict__ w1,
                                              int M, int Woff) {
  __shared__ float As[16][128];   // [o][j]
  __shared__ float Bs[16][128];   // [o][c]
  int t = threadIdx.x;
  int n0 = blockIdx.x * 128;      // c tile
  int m0 = blockIdx.y * 128;      // j tile
  int tm = t >> 4, ts = t & 15;

  float acc[8][8];
#pragma unroll
  for (int i = 0; i < 8; i++)
#pragma unroll
    for (int j = 0; j < 8; j++) acc[i][j] = 0.f;

  for (int k0 = 0; k0 < CIN; k0 += 16) {
#pragma unroll
    for (int i = 0; i < 2; i++) {
      int idx = i * 256 + t;
      int mr = idx >> 2;             // 0..127
      int kq = (idx & 3) << 2;       // 0,4,8,12
      float4 v = make_float4(0.f, 0.f, 0.f, 0.f);
      if (m0 + mr < M) v = *(const float4*)(A + (size_t)(m0 + mr) * CIN + k0 + kq);
      v = tf32r4(v);
      As[kq + 0][mr] = v.x; As[kq + 1][mr] = v.y;
      As[kq + 2][mr] = v.z; As[kq + 3][mr] = v.w;
    }
#pragma unroll
    for (int i = 0; i < 2; i++) {
      int idx = i * 256 + t;
      int kk = idx >> 5;             // 0..15
      int cf = (idx & 31) << 2;      // 0..124
      float4 v = *(const float4*)(w1 + (size_t)(k0 + kk) * CIN + n0 + cf);
      v = tf32r4(v);
      Bs[kk][cf + 0] = v.x; Bs[kk][cf + 1] = v.y;
      Bs[kk][cf + 2] = v.z; Bs[kk][cf + 3] = v.w;
    }
    __syncthreads();
#pragma unroll
    for (int kk = 0; kk < 16; kk++) {
      float4 aA = *(float4*)&As[kk][tm << 2];
      float4 aB = *(float4*)&As[kk][64 + (tm << 2)];
      float4 bA = *(float4*)&Bs[kk][ts << 2];
      float4 bB = *(float4*)&Bs[kk][64 + (ts << 2)];
      float a[8] = {aA.x, aA.y, aA.z, aA.w, aB.x, aB.y, aB.z, aB.w};
      float b[8] = {bA.x, bA.y, bA.z, bA.w, bB.x, bB.y, bB.z, bB.w};
#pragma unroll
      for (int i = 0; i < 8; i++)
#pragma unroll
        for (int j = 0; j < 8; j++) acc[i][j] += a[i] * b[j];
    }
    __syncthreads();
  }

  float* W = (float*)g_W4;
#pragma unroll
  for (int i = 0; i < 8; i++) {
    int ml = (i < 4) ? ((tm << 2) + i) : (64 + (tm << 2) + i - 4);
    int m = m0 + ml;
    if (m >= M) continue;
    float* row = W + (size_t)(Woff + m) * CIN + n0;
    *(float4*)(row + (ts << 2)) = make_float4(acc[i][0], acc[i][1], acc[i][2], acc[i][3]);
    *(float4*)(row + 64 + (ts << 2)) = make_float4(acc[i][4], acc[i][5], acc[i][6], acc[i][7]);
  }
}

// ---------------- 4. folded bias: bias[j] = b_out[j] + dot(A[j,:], b1) ----------------
__global__ void k_bias(const float* __restrict__ wc, const float* __restrict__ wl,
                       const float* __restrict__ bc, const float* __restrict__ bl,
                       const float* __restrict__ b1) {
  int gw = (blockIdx.x * blockDim.x + threadIdx.x) >> 5;
  int lane = threadIdx.x & 31;
  if (gw >= ROWS_TOT) return;
  const float* row = (gw < ROWS_CLS) ? (wc + (size_t)gw * CIN)
                                     : (wl + (size_t)(gw - ROWS_CLS) * CIN);
  float s = 0.f;
  for (int o = lane; o < CIN; o += 32) s += row[o] * b1[o];
#pragma unroll
  for (int off = 16; off; off >>= 1) s += __shfl_xor_sync(0xffffffffu, s, off);
  if (lane == 0) {
    float base = (gw < ROWS_CLS) ? bc[gw] : bl[gw - ROWS_CLS];
    g_bias[gw] = base + s;
  }
}

// ---------------- roi geometry: XLA semantics (byte-identical to passing R6) --------
__device__ __forceinline__ void roi_geom(const float* __restrict__ rois, int r, int p, int q,
                                         int& hs, int& he, int& ws, int& we) {
  float x1 = rois[4 * r + 0], y1 = rois[4 * r + 1];
  float x2 = rois[4 * r + 2], y2 = rois[4 * r + 3];
  float sw = __fmul_rn(rintf(x1), 0.0625f);
  float sh = __fmul_rn(rintf(y1), 0.0625f);
  float ew = __fmul_rn(rintf(__fadd_rn(x2, 1.0f)), 0.0625f);
  float eh = __fmul_rn(rintf(__fadd_rn(y2, 1.0f)), 0.0625f);
  float rw = fmaxf(__fadd_rn(ew, -sw), 0.1f);
  float rh = fmaxf(__fadd_rn(eh, -sh), 0.1f);
  const float RSEV = 1.0f / 7.0f;   // XLA: /7 -> * fl(1/7)
  float bh = __fmul_rn(rh, RSEV);
  float bw = __fmul_rn(rw, RSEV);
  float fp = (float)p, fq = (float)q;
  hs = (int)fminf(fmaxf(floorf(__fadd_rn(__fmul_rn(fp, bh), sh)), 0.f), 50.f);
  he = (int)fminf(fmaxf(ceilf(__fadd_rn(__fmul_rn(__fadd_rn(fp, 1.f), bh), sh)), 0.f), 50.f);
  ws = (int)fminf(fmaxf(floorf(__fadd_rn(__fmul_rn(fq, bw), sw)), 0.f), 50.f);
  we = (int)fminf(fmaxf(ceilf(__fadd_rn(__fmul_rn(__fadd_rn(fq, 1.f), bw), sw)), 0.f), 50.f);
}

// folded weight row for (combined-channel c, bin pq)
__device__ __forceinline__ int row_of(int c, int pq) {
  return (c < NCLS) ? (c * PQN + pq) : (ROWS_CLS + (c - NCLS) * PQN + pq);
}

// ---------------- 5. SAT pool + 25-row projection ----------------
// grid (49 bins, 10 roi groups), 256 threads. 4 SAT lookups per (roi,bin).
__global__ __launch_bounds__(256) void k_pool(const float* __restrict__ rois,
                                              const int* __restrict__ ridx) {
  int pq = blockIdx.x;
  int g = blockIdx.y;
  int p = pq / 7, q = pq - p * 7;
  int tid = threadIdx.x;
  int lane = tid & 31, warp = tid >> 5;

  float4 wreg[COMB];
#pragma unroll
  for (int c = 0; c < COMB; c++)
    wreg[c] = g_W4[(size_t)row_of(c, pq) * 256 + tid];

  __shared__ float red[COMB][8];

  for (int rr = 0; rr < 30; rr++) {
    int r = g * 30 + rr;
    int hs, he, ws, we;
    roi_geom(rois, r, p, q, hs, he, ws, we);
    int n = ridx[r];

    const float4* sat = g_sat4 + (size_t)n * SATSP * 256 + tid;
    float4 s11 = sat[(size_t)(he * SATN + we) * 256];
    float4 s01 = sat[(size_t)(hs * SATN + we) * 256];
    float4 s10 = sat[(size_t)(he * SATN + ws) * 256];
    float4 s00 = sat[(size_t)(hs * SATN + ws) * 256];
    float4 acc = make_float4((s11.x - s01.x) - (s10.x - s00.x),
                             (s11.y - s01.y) - (s10.y - s00.y),
                             (s11.z - s01.z) - (s10.z - s00.z),
                             (s11.w - s01.w) - (s10.w - s00.w));

#pragma unroll
    for (int c = 0; c < COMB; c++) {
      float s = acc.x * wreg[c].x + acc.y * wreg[c].y + acc.z * wreg[c].z + acc.w * wreg[c].w;
#pragma unroll
      for (int off = 16; off; off >>= 1) s += __shfl_xor_sync(0xffffffffu, s, off);
      if (lane == 0) red[c][warp] = s;
    }
    __syncthreads();

    if (tid < COMB) {
      int c = tid;
      float s = 0.f;
#pragma unroll
      for (int w = 0; w < 8; w++) s += red[c][w];
      int cnt = (he - hs) * (we - ws);
      float val = 0.f;
      if (cnt > 0)
        val = __fadd_rn(__fdiv_rn(s, (float)cnt), g_bias[row_of(c, pq)]);
      g_scr[((size_t)r * COMB + c) * PQN + pq] = val;
    }
    __syncthreads();
  }
}

// ---------------- 6. reduce: mean over 49 bins = sum * fl(1/49) ----------------
__global__ void k_reduce(float* __restrict__ out) {
  int idx = blockIdx.x * blockDim.x + threadIdx.x;
  if (idx >= RR * COMB) return;
  int r = idx / COMB, c = idx - r * COMB;
  const float* src = g_scr + (size_t)idx * PQN;
  float s = 0.f;
#pragma unroll
  for (int pq = 0; pq < PQN; pq++) s += src[pq];
  float mean = __fmul_rn(s, 1.0f / 49.0f);
  if (c < NCLS) out[r * NCLS + c] = mean;                  // roi_score [300,21]
  else out[RR * NCLS + r * 4 + (c - NCLS)] = mean;         // roi_locs  [300,4]
}

// ---------------- launch ----------------
extern "C" void kernel_launch(void* const* d_in, const int* in_sizes, int n_in,
                              void* d_out, int out_size) {
  const float* h    = (const float*)d_in[0];
  const float* rois = (const float*)d_in[1];
  const int*   ridx = (const int*)d_in[2];
  const float* w1   = (const float*)d_in[3];
  const float* b1   = (const float*)d_in[4];
  const float* wc   = (const float*)d_in[5];
  const float* bc   = (const float*)d_in[6];
  const float* wl   = (const float*)d_in[7];
  const float* bl   = (const float*)d_in[8];
  float* out = (float*)d_out;

  k_transpose<<<dim3((SPAT + 31) / 32, CIN / 32, NB), dim3(32, 8)>>>(h);
  k_sat1<<<dim3(SATN, NB), 256>>>();
  k_sat2<<<dim3(SATN, NB), 256>>>();
  k_fold<<<dim3(CIN / 128, (ROWS_CLS + 127) / 128), 256>>>(wc, w1, ROWS_CLS, 0);
  k_fold<<<dim3(CIN / 128, (196 + 127) / 128), 256>>>(wl, w1, 196, ROWS_CLS);
  k_bias<<<(ROWS_TOT * 32 + 255) / 256, 256>>>(wc, wl, bc, bl, b1);
  k_pool<<<dim3(PQN, 10), 256>>>(rois, ridx);
  k_reduce<<<(RR * COMB + 255) / 256, 256>>>(out);
}

// round 8
// speedup vs baseline: 2.3760x; 1.5800x over previous
#include <cuda_runtime.h>

#define NB 2
#define CIN 1024
#define HH 50
#define WW 50
#define SPAT 2500
#define SATN 51
#define SATSP (SATN * SATN)
#define RR 300
#define PQN 49
#define NCLS 21
#define ROWS_CLS 1029
#define ROWS_TOT 1225
#define COMB 25

// ---------------- scratch (static device memory; no allocations) ----------------
__device__ float4 g_ht4[(size_t)NB * SPAT * (CIN / 4)];   // tf32(h) channel-last [n][s][c4]
__device__ float4 g_sat4[(size_t)NB * SATSP * (CIN / 4)]; // SAT [n][y*51+x][c4]
__device__ float4 g_Wp4[2][(size_t)ROWS_TOT * (CIN / 4)]; // K-split partial folds
__device__ float4 g_W4[(size_t)ROWS_TOT * (CIN / 4)];     // folded weights, natural row j
__device__ float  g_bias[ROWS_TOT];                       // folded bias
__device__ float  g_scr[(size_t)RR * COMB * PQN];         // per-(roi,c,pq) pooled values

// fp32 -> tf32-rounded fp32
__device__ __forceinline__ float tf32r(float x) {
  unsigned u;
  asm("cvt.rna.tf32.f32 %0, %1;" : "=r"(u) : "f"(x));
  return __uint_as_float(u);
}
__device__ __forceinline__ float4 tf32r4(float4 v) {
  return make_float4(tf32r(v.x), tf32r(v.y), tf32r(v.z), tf32r(v.w));
}

// ---------------- 1. transpose h [n,c,s] -> ht [n,s,c], tf32-rounded ----------------
__global__ void k_transpose(const float* __restrict__ h) {
  __shared__ float tile[32][33];
  int n = blockIdx.z;
  int s0 = blockIdx.x * 32, c0 = blockIdx.y * 32;
  int tx = threadIdx.x, ty = threadIdx.y;
  float* ht = (float*)g_ht4;
#pragma unroll
  for (int i = 0; i < 32; i += 8) {
    int c = c0 + ty + i, s = s0 + tx;
    if (c < CIN && s < SPAT) tile[ty + i][tx] = h[((size_t)n * CIN + c) * SPAT + s];
  }
  __syncthreads();
#pragma unroll
  for (int i = 0; i < 32; i += 8) {
    int s = s0 + ty + i, c = c0 + tx;
    if (s < SPAT && c < CIN) ht[((size_t)n * SPAT + s) * CIN + c] = tf32r(tile[tx][ty + i]);
  }
}

// ---------------- 2a. SAT pass 1: prefix along x ----------------
__global__ __launch_bounds__(256) void k_sat1() {
  int by = blockIdx.x;
  int n = blockIdx.y;
  int tid = threadIdx.x;
  float4* satb = g_sat4 + (size_t)n * SATSP * 256;
  if (by == 0) {
    float4 z = make_float4(0.f, 0.f, 0.f, 0.f);
    for (int x = 0; x < SATN; x++) satb[(size_t)x * 256 + tid] = z;
    return;
  }
  int y = by - 1;
  const float4* src = g_ht4 + ((size_t)n * SPAT + y * WW) * 256 + tid;
  float4* dst = satb + (size_t)(by * SATN) * 256 + tid;
  float4 acc = make_float4(0.f, 0.f, 0.f, 0.f);
  dst[0] = acc;
#pragma unroll 5
  for (int x = 0; x < WW; x++) {
    float4 v = src[(size_t)x * 256];
    acc.x += v.x; acc.y += v.y; acc.z += v.z; acc.w += v.w;
    dst[(size_t)(x + 1) * 256] = acc;
  }
}

// ---------------- 2b. SAT pass 2: prefix along y (in place) ----------------
__global__ __launch_bounds__(256) void k_sat2() {
  int x = blockIdx.x;
  int n = blockIdx.y;
  int tid = threadIdx.x;
  float4* p = g_sat4 + ((size_t)n * SATSP + x) * 256 + tid;
  float4 acc = make_float4(0.f, 0.f, 0.f, 0.f);
#pragma unroll 5
  for (int y = 1; y < SATN; y++) {
    float4 v = p[(size_t)(y * SATN) * 256];
    acc.x += v.x; acc.y += v.y; acc.z += v.z; acc.w += v.w;
    p[(size_t)(y * SATN) * 256] = acc;
  }
}

// ---------------- 3. fold GEMM: Wp[kz][j,c] = sum_{o in half kz} A[j,o]*w1[o,c] -----
// 64x64 tiles, 128 threads, 8x4 micro, K-split 2. grid (16, 20, 2) = 640 blocks.
__global__ __launch_bounds__(128) void k_fold(const float* __restrict__ wc,
                                              const float* __restrict__ wl,
                                              const float* __restrict__ w1) {
  __shared__ float As[16][64];    // [k][m]
  __shared__ float Bs[16][68];    // [k][n] (padded)
  int t = threadIdx.x;
  int n0 = blockIdx.x * 64;       // c tile
  int m0 = blockIdx.y * 64;       // j tile
  int kz = blockIdx.z;            // K half
  int tx = t & 15, ty = t >> 4;   // tx: n (16x4), ty: m (8x8)

  float acc[8][4];
#pragma unroll
  for (int i = 0; i < 8; i++)
#pragma unroll
    for (int j = 0; j < 4; j++) acc[i][j] = 0.f;

  int kbeg = kz * 512, kend = kbeg + 512;
  for (int k0 = kbeg; k0 < kend; k0 += 16) {
    // A tile: 64 rows x 16 k = 256 float4, 2 per thread
#pragma unroll
    for (int i = 0; i < 2; i++) {
      int idx = i * 128 + t;
      int row = idx >> 2;             // 0..63
      int kq = (idx & 3) << 2;        // 0,4,8,12
      int gm = m0 + row;
      float4 v = make_float4(0.f, 0.f, 0.f, 0.f);
      if (gm < ROWS_TOT) {
        const float* ap = (gm < ROWS_CLS) ? (wc + (size_t)gm * CIN)
                                          : (wl + (size_t)(gm - ROWS_CLS) * CIN);
        v = tf32r4(*(const float4*)(ap + k0 + kq));
      }
      As[kq + 0][row] = v.x; As[kq + 1][row] = v.y;
      As[kq + 2][row] = v.z; As[kq + 3][row] = v.w;
    }
    // B tile: 16 k x 64 c = 256 float4, 2 per thread
#pragma unroll
    for (int i = 0; i < 2; i++) {
      int idx = i * 128 + t;
      int kr = idx >> 4;              // 0..15
      int nc = (idx & 15) << 2;       // 0..60
      float4 v = tf32r4(*(const float4*)(w1 + (size_t)(k0 + kr) * CIN + n0 + nc));
      Bs[kr][nc + 0] = v.x; Bs[kr][nc + 1] = v.y;
      Bs[kr][nc + 2] = v.z; Bs[kr][nc + 3] = v.w;
    }
    __syncthreads();
#pragma unroll
    for (int kk = 0; kk < 16; kk++) {
      float4 a0 = *(float4*)&As[kk][ty << 3];
      float4 a1 = *(float4*)&As[kk][(ty << 3) + 4];
      float4 b = *(float4*)&Bs[kk][tx << 2];
      float a[8] = {a0.x, a0.y, a0.z, a0.w, a1.x, a1.y, a1.z, a1.w};
      float bb[4] = {b.x, b.y, b.z, b.w};
#pragma unroll
      for (int i = 0; i < 8; i++)
#pragma unroll
        for (int j = 0; j < 4; j++) acc[i][j] += a[i] * bb[j];
    }
    __syncthreads();
  }

  float* Wp = (float*)g_Wp4[kz];
#pragma unroll
  for (int i = 0; i < 8; i++) {
    int gm = m0 + (ty << 3) + i;
    if (gm < ROWS_TOT)
      *(float4*)(Wp + (size_t)gm * CIN + n0 + (tx << 2)) =
          make_float4(acc[i][0], acc[i][1], acc[i][2], acc[i][3]);
  }
}

// ---------------- 3b. sum K-split partials ----------------
__global__ void k_wsum() {
  size_t i = (size_t)blockIdx.x * 256 + threadIdx.x;
  if (i >= (size_t)ROWS_TOT * 256) return;
  float4 a = g_Wp4[0][i], b = g_Wp4[1][i];
  g_W4[i] = make_float4(a.x + b.x, a.y + b.y, a.z + b.z, a.w + b.w);
}

// ---------------- 4. folded bias: bias[j] = b_out[j] + dot(A[j,:], b1) ----------------
__global__ void k_bias(const float* __restrict__ wc, const float* __restrict__ wl,
                       const float* __restrict__ bc, const float* __restrict__ bl,
                       const float* __restrict__ b1) {
  int gw = (blockIdx.x * blockDim.x + threadIdx.x) >> 5;
  int lane = threadIdx.x & 31;
  if (gw >= ROWS_TOT) return;
  const float* row = (gw < ROWS_CLS) ? (wc + (size_t)gw * CIN)
                                     : (wl + (size_t)(gw - ROWS_CLS) * CIN);
  float s = 0.f;
  for (int o = lane; o < CIN; o += 32) s += row[o] * b1[o];
#pragma unroll
  for (int off = 16; off; off >>= 1) s += __shfl_xor_sync(0xffffffffu, s, off);
  if (lane == 0) {
    float base = (gw < ROWS_CLS) ? bc[gw] : bl[gw - ROWS_CLS];
    g_bias[gw] = base + s;
  }
}

// ---------------- roi geometry: XLA semantics (byte-identical to passing R6/R7) -----
__device__ __forceinline__ void roi_geom(const float* __restrict__ rois, int r, int p, int q,
                                         int& hs, int& he, int& ws, int& we) {
  float x1 = rois[4 * r + 0], y1 = rois[4 * r + 1];
  float x2 = rois[4 * r + 2], y2 = rois[4 * r + 3];
  float sw = __fmul_rn(rintf(x1), 0.0625f);
  float sh = __fmul_rn(rintf(y1), 0.0625f);
  float ew = __fmul_rn(rintf(__fadd_rn(x2, 1.0f)), 0.0625f);
  float eh = __fmul_rn(rintf(__fadd_rn(y2, 1.0f)), 0.0625f);
  float rw = fmaxf(__fadd_rn(ew, -sw), 0.1f);
  float rh = fmaxf(__fadd_rn(eh, -sh), 0.1f);
  const float RSEV = 1.0f / 7.0f;   // XLA: /7 -> * fl(1/7)
  float bh = __fmul_rn(rh, RSEV);
  float bw = __fmul_rn(rw, RSEV);
  float fp = (float)p, fq = (float)q;
  hs = (int)fminf(fmaxf(floorf(__fadd_rn(__fmul_rn(fp, bh), sh)), 0.f), 50.f);
  he = (int)fminf(fmaxf(ceilf(__fadd_rn(__fmul_rn(__fadd_rn(fp, 1.f), bh), sh)), 0.f), 50.f);
  ws = (int)fminf(fmaxf(floorf(__fadd_rn(__fmul_rn(fq, bw), sw)), 0.f), 50.f);
  we = (int)fminf(fmaxf(ceilf(__fadd_rn(__fmul_rn(__fadd_rn(fq, 1.f), bw), sw)), 0.f), 50.f);
}

// folded weight row for (combined-channel c, bin pq)
__device__ __forceinline__ int row_of(int c, int pq) {
  return (c < NCLS) ? (c * PQN + pq) : (ROWS_CLS + (c - NCLS) * PQN + pq);
}

// ---------------- 5. SAT pool + 25-row projection ----------------
__global__ __launch_bounds__(256) void k_pool(const float* __restrict__ rois,
                                              const int* __restrict__ ridx) {
  int pq = blockIdx.x;
  int g = blockIdx.y;
  int p = pq / 7, q = pq - p * 7;
  int tid = threadIdx.x;
  int lane = tid & 31, warp = tid >> 5;

  float4 wreg[COMB];
#pragma unroll
  for (int c = 0; c < COMB; c++)
    wreg[c] = g_W4[(size_t)row_of(c, pq) * 256 + tid];

  __shared__ float red[COMB][8];

  for (int rr = 0; rr < 30; rr++) {
    int r = g * 30 + rr;
    int hs, he, ws, we;
    roi_geom(rois, r, p, q, hs, he, ws, we);
    int n = ridx[r];

    const float4* sat = g_sat4 + (size_t)n * SATSP * 256 + tid;
    float4 s11 = sat[(size_t)(he * SATN + we) * 256];
    float4 s01 = sat[(size_t)(hs * SATN + we) * 256];
    float4 s10 = sat[(size_t)(he * SATN + ws) * 256];
    float4 s00 = sat[(size_t)(hs * SATN + ws) * 256];
    float4 acc = make_float4((s11.x - s01.x) - (s10.x - s00.x),
                             (s11.y - s01.y) - (s10.y - s00.y),
                             (s11.z - s01.z) - (s10.z - s00.z),
                             (s11.w - s01.w) - (s10.w - s00.w));

#pragma unroll
    for (int c = 0; c < COMB; c++) {
      float s = acc.x * wreg[c].x + acc.y * wreg[c].y + acc.z * wreg[c].z + acc.w * wreg[c].w;
#pragma unroll
      for (int off = 16; off; off >>= 1) s += __shfl_xor_sync(0xffffffffu, s, off);
      if (lane == 0) red[c][warp] = s;
    }
    __syncthreads();

    if (tid < COMB) {
      int c = tid;
      float s = 0.f;
#pragma unroll
      for (int w = 0; w < 8; w++) s += red[c][w];
      int cnt = (he - hs) * (we - ws);
      float val = 0.f;
      if (cnt > 0)
        val = __fadd_rn(__fdiv_rn(s, (float)cnt), g_bias[row_of(c, pq)]);
      g_scr[((size_t)r * COMB + c) * PQN + pq] = val;
    }
    __syncthreads();
  }
}

// ---------------- 6. reduce: mean over 49 bins = sum * fl(1/49) ----------------
__global__ void k_reduce(float* __restrict__ out) {
  int idx = blockIdx.x * blockDim.x + threadIdx.x;
  if (idx >= RR * COMB) return;
  int r = idx / COMB, c = idx - r * COMB;
  const float* src = g_scr + (size_t)idx * PQN;
  float s = 0.f;
#pragma unroll
  for (int pq = 0; pq < PQN; pq++) s += src[pq];
  float mean = __fmul_rn(s, 1.0f / 49.0f);
  if (c < NCLS) out[r * NCLS + c] = mean;                  // roi_score [300,21]
  else out[RR * NCLS + r * 4 + (c - NCLS)] = mean;         // roi_locs  [300,4]
}

// ---------------- launch ----------------
extern "C" void kernel_launch(void* const* d_in, const int* in_sizes, int n_in,
                              void* d_out, int out_size) {
  const float* h    = (const float*)d_in[0];
  const float* rois = (const float*)d_in[1];
  const int*   ridx = (const int*)d_in[2];
  const float* w1   = (const float*)d_in[3];
  const float* b1   = (const float*)d_in[4];
  const float* wc   = (const float*)d_in[5];
  const float* bc   = (const float*)d_in[6];
  const float* wl   = (const float*)d_in[7];
  const float* bl   = (const float*)d_in[8];
  float* out = (float*)d_out;

  k_fold<<<dim3(CIN / 64, (ROWS_TOT + 63) / 64, 2), 128>>>(wc, wl, w1);
  k_transpose<<<dim3((SPAT + 31) / 32, CIN / 32, NB), dim3(32, 8)>>>(h);
  k_sat1<<<dim3(SATN, NB), 256>>>();
  k_sat2<<<dim3(SATN, NB), 256>>>();
  k_wsum<<<(ROWS_TOT * 256 + 255) / 256, 256>>>();
  k_bias<<<(ROWS_TOT * 32 + 255) / 256, 256>>>(wc, wl, bc, bl, b1);
  k_pool<<<dim3(PQN, 10), 256>>>(rois, ridx);
  k_reduce<<<(RR * COMB + 255) / 256, 256>>>(out);
}

// round 9
// speedup vs baseline: 2.8881x; 1.2155x over previous
#include <cuda_runtime.h>
#include <cstdint>

#define NB 2
#define CIN 1024
#define HH 50
#define WW 50
#define SPAT 2500
#define SATN 51
#define SATSP (SATN * SATN)
#define RR 300
#define PQN 49
#define NCLS 21
#define ROWS_CLS 1029
#define ROWS_TOT 1225
#define COMB 25

// ---------------- scratch (static device memory; no allocations) ----------------
__device__ float4 g_ht4[(size_t)NB * SPAT * (CIN / 4)];   // tf32(h) channel-last [n][s][c4]
__device__ float4 g_sat4[(size_t)NB * SATSP * (CIN / 4)]; // SAT [n][y*51+x][c4]
__device__ float4 g_W4[(size_t)ROWS_TOT * (CIN / 4)];     // folded weights, natural row j
__device__ float  g_bias[ROWS_TOT];                       // folded bias
__device__ float  g_scr[(size_t)RR * COMB * PQN];         // per-(roi,c,pq) pooled values

// fp32 -> tf32-rounded fp32
__device__ __forceinline__ float tf32r(float x) {
  unsigned u;
  asm("cvt.rna.tf32.f32 %0, %1;" : "=r"(u) : "f"(x));
  return __uint_as_float(u);
}
__device__ __forceinline__ float4 tf32r4(float4 v) {
  return make_float4(tf32r(v.x), tf32r(v.y), tf32r(v.z), tf32r(v.w));
}

// ---------------- 1. transpose h [n,c,s] -> ht [n,s,c], tf32-rounded ----------------
__global__ void k_transpose(const float* __restrict__ h) {
  __shared__ float tile[32][33];
  int n = blockIdx.z;
  int s0 = blockIdx.x * 32, c0 = blockIdx.y * 32;
  int tx = threadIdx.x, ty = threadIdx.y;
  float* ht = (float*)g_ht4;
#pragma unroll
  for (int i = 0; i < 32; i += 8) {
    int c = c0 + ty + i, s = s0 + tx;
    if (c < CIN && s < SPAT) tile[ty + i][tx] = h[((size_t)n * CIN + c) * SPAT + s];
  }
  __syncthreads();
#pragma unroll
  for (int i = 0; i < 32; i += 8) {
    int s = s0 + ty + i, c = c0 + tx;
    if (s < SPAT && c < CIN) ht[((size_t)n * SPAT + s) * CIN + c] = tf32r(tile[tx][ty + i]);
  }
}

// ---------------- 2a. SAT pass 1: prefix along x ----------------
__global__ __launch_bounds__(256) void k_sat1() {
  int by = blockIdx.x;
  int n = blockIdx.y;
  int tid = threadIdx.x;
  float4* satb = g_sat4 + (size_t)n * SATSP * 256;
  if (by == 0) {
    float4 z = make_float4(0.f, 0.f, 0.f, 0.f);
    for (int x = 0; x < SATN; x++) satb[(size_t)x * 256 + tid] = z;
    return;
  }
  int y = by - 1;
  const float4* src = g_ht4 + ((size_t)n * SPAT + y * WW) * 256 + tid;
  float4* dst = satb + (size_t)(by * SATN) * 256 + tid;
  float4 acc = make_float4(0.f, 0.f, 0.f, 0.f);
  dst[0] = acc;
#pragma unroll 5
  for (int x = 0; x < WW; x++) {
    float4 v = src[(size_t)x * 256];
    acc.x += v.x; acc.y += v.y; acc.z += v.z; acc.w += v.w;
    dst[(size_t)(x + 1) * 256] = acc;
  }
}

// ---------------- 2b. SAT pass 2: prefix along y (in place) ----------------
__global__ __launch_bounds__(256) void k_sat2() {
  int x = blockIdx.x;
  int n = blockIdx.y;
  int tid = threadIdx.x;
  float4* p = g_sat4 + ((size_t)n * SATSP + x) * 256 + tid;
  float4 acc = make_float4(0.f, 0.f, 0.f, 0.f);
#pragma unroll 5
  for (int y = 1; y < SATN; y++) {
    float4 v = p[(size_t)(y * SATN) * 256];
    acc.x += v.x; acc.y += v.y; acc.z += v.z; acc.w += v.w;
    p[(size_t)(y * SATN) * 256] = acc;
  }
}

// ---------------- 3. fold GEMM via tensor cores (tf32 mma.sync) ----------------
// W[j,c] = sum_o tf32(A[j,o]) * tf32(w1[o,c]).  M=1225, N=1024, K=1024.
// Block: 256 thr = 8 warps (2m x 4n of 32x32 warp tiles) -> 64x128 block tile.
// Grid (8, 20) = 160 blocks. K-tile 32 via smem.
#define KT 32
#define APAD 36
#define BPAD 132
__global__ __launch_bounds__(256) void k_fold_mma(const float* __restrict__ wc,
                                                  const float* __restrict__ wl,
                                                  const float* __restrict__ w1) {
  __shared__ float As[64][APAD];    // [m][k]
  __shared__ float Bs[KT][BPAD];    // [k][n]
  int t = threadIdx.x;
  int warp = t >> 5, lane = t & 31;
  int n0 = blockIdx.x * 128;
  int m0 = blockIdx.y * 64;
  int warpM = warp >> 2, warpN = warp & 3;     // 2 x 4
  int mb = warpM * 32, nb = warpN * 32;
  int lg = lane >> 2;      // 0..7
  int lt = lane & 3;       // 0..3

  float c0[2][4], c1[2][4], c2[2][4], c3[2][4];
#pragma unroll
  for (int i = 0; i < 2; i++)
#pragma unroll
    for (int j = 0; j < 4; j++) { c0[i][j] = c1[i][j] = c2[i][j] = c3[i][j] = 0.f; }

  for (int k0 = 0; k0 < CIN; k0 += KT) {
    // As: 64 rows x 32 k  (512 float4, 2/thread)
#pragma unroll
    for (int i = 0; i < 2; i++) {
      int idx = i * 256 + t;
      int row = idx >> 3;             // 0..63
      int kq = (idx & 7) << 2;        // 0..28
      int gm = m0 + row;
      float4 v = make_float4(0.f, 0.f, 0.f, 0.f);
      if (gm < ROWS_TOT) {
        const float* ap = (gm < ROWS_CLS) ? (wc + (size_t)gm * CIN)
                                          : (wl + (size_t)(gm - ROWS_CLS) * CIN);
        v = tf32r4(*(const float4*)(ap + k0 + kq));
      }
      *(float4*)&As[row][kq] = v;
    }
    // Bs: 32 k x 128 n (1024 float4, 4/thread)
#pragma unroll
    for (int i = 0; i < 4; i++) {
      int idx = i * 256 + t;
      int kr = idx >> 5;              // 0..31
      int nq = (idx & 31) << 2;       // 0..124
      float4 v = tf32r4(*(const float4*)(w1 + (size_t)(k0 + kr) * CIN + n0 + nq));
      *(float4*)&Bs[kr][nq] = v;
    }
    __syncthreads();

#pragma unroll
    for (int ks = 0; ks < 4; ks++) {
      int kc = ks << 3;
      // A fragments for 2 m-subtiles
      uint32_t a[2][4];
#pragma unroll
      for (int ms = 0; ms < 2; ms++) {
        int row = mb + (ms << 4) + lg;
        a[ms][0] = __float_as_uint(As[row][kc + lt]);
        a[ms][1] = __float_as_uint(As[row + 8][kc + lt]);
        a[ms][2] = __float_as_uint(As[row][kc + 4 + lt]);
        a[ms][3] = __float_as_uint(As[row + 8][kc + 4 + lt]);
      }
      // B fragments for 4 n-subtiles
      uint32_t b[4][2];
#pragma unroll
      for (int ns = 0; ns < 4; ns++) {
        int col = nb + (ns << 3) + lg;
        b[ns][0] = __float_as_uint(Bs[kc + lt][col]);
        b[ns][1] = __float_as_uint(Bs[kc + 4 + lt][col]);
      }
#pragma unroll
      for (int ms = 0; ms < 2; ms++)
#pragma unroll
        for (int ns = 0; ns < 4; ns++) {
          asm volatile(
            "mma.sync.aligned.m16n8k8.row.col.f32.tf32.tf32.f32 "
            "{%0,%1,%2,%3}, {%4,%5,%6,%7}, {%8,%9}, {%0,%1,%2,%3};"
            : "+f"(c0[ms][ns]), "+f"(c1[ms][ns]), "+f"(c2[ms][ns]), "+f"(c3[ms][ns])
            : "r"(a[ms][0]), "r"(a[ms][1]), "r"(a[ms][2]), "r"(a[ms][3]),
              "r"(b[ns][0]), "r"(b[ns][1]));
        }
    }
    __syncthreads();
  }

  // epilogue: c0,c1 at (row, col), c2,c3 at (row+8, col); col = 2*lt within 8-wide subtile
  float* W = (float*)g_W4;
#pragma unroll
  for (int ms = 0; ms < 2; ms++) {
    int gr = m0 + mb + (ms << 4) + lg;
#pragma unroll
    for (int ns = 0; ns < 4; ns++) {
      int gc = n0 + nb + (ns << 3) + (lt << 1);
      if (gr < ROWS_TOT)
        *(float2*)(W + (size_t)gr * CIN + gc) = make_float2(c0[ms][ns], c1[ms][ns]);
      if (gr + 8 < ROWS_TOT)
        *(float2*)(W + (size_t)(gr + 8) * CIN + gc) = make_float2(c2[ms][ns], c3[ms][ns]);
    }
  }
}

// ---------------- 4. folded bias: bias[j] = b_out[j] + dot(A[j,:], b1) ----------------
__global__ void k_bias(const float* __restrict__ wc, const float* __restrict__ wl,
                       const float* __restrict__ bc, const float* __restrict__ bl,
                       const float* __restrict__ b1) {
  int gw = (blockIdx.x * blockDim.x + threadIdx.x) >> 5;
  int lane = threadIdx.x & 31;
  if (gw >= ROWS_TOT) return;
  const float* row = (gw < ROWS_CLS) ? (wc + (size_t)gw * CIN)
                                     : (wl + (size_t)(gw - ROWS_CLS) * CIN);
  float s = 0.f;
  for (int o = lane; o < CIN; o += 32) s += row[o] * b1[o];
#pragma unroll
  for (int off = 16; off; off >>= 1) s += __shfl_xor_sync(0xffffffffu, s, off);
  if (lane == 0) {
    float base = (gw < ROWS_CLS) ? bc[gw] : bl[gw - ROWS_CLS];
    g_bias[gw] = base + s;
  }
}

// ---------------- roi geometry: XLA semantics (byte-identical to passing rounds) ----
__device__ __forceinline__ void roi_geom(const float* __restrict__ rois, int r, int p, int q,
                                         int& hs, int& he, int& ws, int& we) {
  float x1 = rois[4 * r + 0], y1 = rois[4 * r + 1];
  float x2 = rois[4 * r + 2], y2 = rois[4 * r + 3];
  float sw = __fmul_rn(rintf(x1), 0.0625f);
  float sh = __fmul_rn(rintf(y1), 0.0625f);
  float ew = __fmul_rn(rintf(__fadd_rn(x2, 1.0f)), 0.0625f);
  float eh = __fmul_rn(rintf(__fadd_rn(y2, 1.0f)), 0.0625f);
  float rw = fmaxf(__fadd_rn(ew, -sw), 0.1f);
  float rh = fmaxf(__fadd_rn(eh, -sh), 0.1f);
  const float RSEV = 1.0f / 7.0f;   // XLA: /7 -> * fl(1/7)
  float bh = __fmul_rn(rh, RSEV);
  float bw = __fmul_rn(rw, RSEV);
  float fp = (float)p, fq = (float)q;
  hs = (int)fminf(fmaxf(floorf(__fadd_rn(__fmul_rn(fp, bh), sh)), 0.f), 50.f);
  he = (int)fminf(fmaxf(ceilf(__fadd_rn(__fmul_rn(__fadd_rn(fp, 1.f), bh), sh)), 0.f), 50.f);
  ws = (int)fminf(fmaxf(floorf(__fadd_rn(__fmul_rn(fq, bw), sw)), 0.f), 50.f);
  we = (int)fminf(fmaxf(ceilf(__fadd_rn(__fmul_rn(__fadd_rn(fq, 1.f), bw), sw)), 0.f), 50.f);
}

// folded weight row for (combined-channel c, bin pq)
__device__ __forceinline__ int row_of(int c, int pq) {
  return (c < NCLS) ? (c * PQN + pq) : (ROWS_CLS + (c - NCLS) * PQN + pq);
}

// ---------------- 5. SAT pool + 25-row projection ----------------
__global__ __launch_bounds__(256) void k_pool(const float* __restrict__ rois,
                                              const int* __restrict__ ridx) {
  int pq = blockIdx.x;
  int g = blockIdx.y;
  int p = pq / 7, q = pq - p * 7;
  int tid = threadIdx.x;
  int lane = tid & 31, warp = tid >> 5;

  float4 wreg[COMB];
#pragma unroll
  for (int c = 0; c < COMB; c++)
    wreg[c] = g_W4[(size_t)row_of(c, pq) * 256 + tid];

  __shared__ float red[COMB][8];

  for (int rr = 0; rr < 30; rr++) {
    int r = g * 30 + rr;
    int hs, he, ws, we;
    roi_geom(rois, r, p, q, hs, he, ws, we);
    int n = ridx[r];

    const float4* sat = g_sat4 + (size_t)n * SATSP * 256 + tid;
    float4 s11 = sat[(size_t)(he * SATN + we) * 256];
    float4 s01 = sat[(size_t)(hs * SATN + we) * 256];
    float4 s10 = sat[(size_t)(he * SATN + ws) * 256];
    float4 s00 = sat[(size_t)(hs * SATN + ws) * 256];
    float4 acc = make_float4((s11.x - s01.x) - (s10.x - s00.x),
                             (s11.y - s01.y) - (s10.y - s00.y),
                             (s11.z - s01.z) - (s10.z - s00.z),
                             (s11.w - s01.w) - (s10.w - s00.w));

#pragma unroll
    for (int c = 0; c < COMB; c++) {
      float s = acc.x * wreg[c].x + acc.y * wreg[c].y + acc.z * wreg[c].z + acc.w * wreg[c].w;
#pragma unroll
      for (int off = 16; off; off >>= 1) s += __shfl_xor_sync(0xffffffffu, s, off);
      if (lane == 0) red[c][warp] = s;
    }
    __syncthreads();

    if (tid < COMB) {
      int c = tid;
      float s = 0.f;
#pragma unroll
      for (int w = 0; w < 8; w++) s += red[c][w];
      int cnt = (he - hs) * (we - ws);
      float val = 0.f;
      if (cnt > 0)
        val = __fadd_rn(__fdiv_rn(s, (float)cnt), g_bias[row_of(c, pq)]);
      g_scr[((size_t)r * COMB + c) * PQN + pq] = val;
    }
    __syncthreads();
  }
}

// ---------------- 6. reduce: mean over 49 bins = sum * fl(1/49) ----------------
__global__ void k_reduce(float* __restrict__ out) {
  int idx = blockIdx.x * blockDim.x + threadIdx.x;
  if (idx >= RR * COMB) return;
  int r = idx / COMB, c = idx - r * COMB;
  const float* src = g_scr + (size_t)idx * PQN;
  float s = 0.f;
#pragma unroll
  for (int pq = 0; pq < PQN; pq++) s += src[pq];
  float mean = __fmul_rn(s, 1.0f / 49.0f);
  if (c < NCLS) out[r * NCLS + c] = mean;                  // roi_score [300,21]
  else out[RR * NCLS + r * 4 + (c - NCLS)] = mean;         // roi_locs  [300,4]
}

// ---------------- launch ----------------
extern "C" void kernel_launch(void* const* d_in, const int* in_sizes, int n_in,
                              void* d_out, int out_size) {
  const float* h    = (const float*)d_in[0];
  const float* rois = (const float*)d_in[1];
  const int*   ridx = (const int*)d_in[2];
  const float* w1   = (const float*)d_in[3];
  const float* b1   = (const float*)d_in[4];
  const float* wc   = (const float*)d_in[5];
  const float* bc   = (const float*)d_in[6];
  const float* wl   = (const float*)d_in[7];
  const float* bl   = (const float*)d_in[8];
  float* out = (float*)d_out;

  k_fold_mma<<<dim3(CIN / 128, (ROWS_TOT + 63) / 64), 256>>>(wc, wl, w1);
  k_transpose<<<dim3((SPAT + 31) / 32, CIN / 32, NB), dim3(32, 8)>>>(h);
  k_sat1<<<dim3(SATN, NB), 256>>>();
  k_sat2<<<dim3(SATN, NB), 256>>>();
  k_bias<<<(ROWS_TOT * 32 + 255) / 256, 256>>>(wc, wl, bc, bl, b1);
  k_pool<<<dim3(PQN, 10), 256>>>(rois, ridx);
  k_reduce<<<(RR * COMB + 255) / 256, 256>>>(out);
}